// round 10
// baseline (speedup 1.0000x reference)
#include <cuda_runtime.h>
#include <cuda_bf16.h>
#include <cuda_fp16.h>
#include <cstdint>

#define N_NODES 50000
#define NFEAT 256
#define NHID 64
#define NCLASS 16
#define N_EDGES 1600000
#define SCAN_BLK 1024
#define NBLK ((N_NODES + SCAN_BLK - 1) / SCAN_BLK)

// Scratch (no dynamic allocation allowed)
__device__ __half g_sup1[N_NODES * NHID];   // x @ W1   (fp16)
__device__ float  g_hacc[N_NODES * NHID];   // spmm1 result (fp32)
__device__ __half g_sup2[N_NODES * NCLASS]; // relu(h) @ W2 (fp16)
__device__ int   g_deg[N_NODES];
__device__ int   g_off[N_NODES];
__device__ int   g_cursor[N_NODES];
__device__ int   g_bagg[NBLK];              // per-block aggregates (lookback scan)
__device__ int   g_bflag[NBLK];             // publish flags (zeroed per call)
__device__ int2  g_csr[N_EDGES];            // packed (src, weight-bits), sorted by dst
__device__ __nv_bfloat16 g_w1t_hi[NHID * NFEAT];  // W1^T split hi  [n][k]
__device__ __nv_bfloat16 g_w1t_lo[NHID * NFEAT];  // W1^T split lo  [n][k]

// ============================ helpers ======================================
__device__ __forceinline__ uint32_t smem_u32(const void* p) {
    uint32_t a;
    asm("{ .reg .u64 t; cvta.to.shared.u64 t, %1; cvt.u32.u64 %0, t; }"
        : "=r"(a) : "l"(p));
    return a;
}

__device__ __forceinline__ void ldm_x4(uint32_t* r, uint32_t addr) {
    asm volatile("ldmatrix.sync.aligned.m8n8.x4.shared.b16 {%0,%1,%2,%3}, [%4];"
                 : "=r"(r[0]), "=r"(r[1]), "=r"(r[2]), "=r"(r[3]) : "r"(addr));
}

__device__ __forceinline__ void mma_bf16(float* d, const uint32_t* a,
                                         uint32_t b0, uint32_t b1) {
    asm volatile("mma.sync.aligned.m16n8k16.row.col.f32.bf16.bf16.f32 "
                 "{%0,%1,%2,%3}, {%4,%5,%6,%7}, {%8,%9}, {%0,%1,%2,%3};"
                 : "+f"(d[0]), "+f"(d[1]), "+f"(d[2]), "+f"(d[3])
                 : "r"(a[0]), "r"(a[1]), "r"(a[2]), "r"(a[3]), "r"(b0), "r"(b1));
}

#define SWZ(off) ((off) ^ (((off) >> 3) & 0x70))

// ---------------------------------------------------------------------------
// Histogram + W1 prep fused. Blocks [0,64) also transpose/split W1.
// ---------------------------------------------------------------------------
__global__ void histprep_kernel(const int* __restrict__ dst, int* __restrict__ deg,
                                const float* __restrict__ W1,
                                __nv_bfloat16* __restrict__ hi,
                                __nv_bfloat16* __restrict__ lo, int E) {
    int i = blockIdx.x * blockDim.x + threadIdx.x;

    if (blockIdx.x < 64) {  // 64*256 = 16384 = NHID*NFEAT
        int n = i >> 8, k = i & 255;
        float v = __ldg(W1 + k * NHID + n);
        __nv_bfloat16 h = __float2bfloat16(v);
        hi[i] = h;
        lo[i] = __float2bfloat16(v - __bfloat162float(h));
    }

    int stride = gridDim.x * blockDim.x;
    for (int e = i; e < E; e += stride)
        atomicAdd(deg + __ldg(dst + e), 1);
}

// ---------------------------------------------------------------------------
// Single-pass exclusive scan with decoupled lookback (49 blocks, all resident).
// Writes off[] and cursor[] directly.
// ---------------------------------------------------------------------------
__global__ void scan_fused_kernel(const int* __restrict__ deg,
                                  int* __restrict__ off, int* __restrict__ cursor,
                                  volatile int* __restrict__ bagg,
                                  volatile int* __restrict__ bflag, int n) {
    __shared__ int warp_sums[32];
    __shared__ int s_excl;
    const int bid = blockIdx.x;
    const int i = bid * SCAN_BLK + threadIdx.x;
    const int v = (i < n) ? deg[i] : 0;
    const int lane = threadIdx.x & 31, wid = threadIdx.x >> 5;

    int incl = v;
#pragma unroll
    for (int o = 1; o < 32; o <<= 1) {
        int t = __shfl_up_sync(0xffffffffu, incl, o);
        if (lane >= o) incl += t;
    }
    if (lane == 31) warp_sums[wid] = incl;
    __syncthreads();
    if (wid == 0) {
        int s = warp_sums[lane];
#pragma unroll
        for (int o = 1; o < 32; o <<= 1) {
            int t = __shfl_up_sync(0xffffffffu, s, o);
            if (lane >= o) s += t;
        }
        warp_sums[lane] = s;
    }
    __syncthreads();
    int wpre = (wid == 0) ? 0 : warp_sums[wid - 1];
    int local_incl = wpre + incl;

    // Publish block aggregate ASAP
    if (threadIdx.x == SCAN_BLK - 1) {
        bagg[bid] = local_incl;
        __threadfence();
        bflag[bid] = 1;
    }

    // Lookback: warp 1 sums predecessors' aggregates
    if (wid == 1) {
        int sum = 0;
        for (int p = lane; p < bid; p += 32) {
            while (bflag[p] == 0) { }
            sum += bagg[p];
        }
#pragma unroll
        for (int o = 16; o >= 1; o >>= 1)
            sum += __shfl_xor_sync(0xffffffffu, sum, o);
        if (lane == 0) s_excl = sum;
    }
    __syncthreads();

    int excl = s_excl + local_incl - v;
    if (i < n) {
        off[i] = excl;
        cursor[i] = excl;
    }
}

__global__ void scatter_kernel(const int* __restrict__ src, const int* __restrict__ dst,
                               const float* __restrict__ w, int* __restrict__ cursor,
                               int2* __restrict__ csr, int E) {
    int i = blockIdx.x * blockDim.x + threadIdx.x;
    int stride = gridDim.x * blockDim.x;
    for (int e = i; e < E; e += stride) {
        int d = __ldg(dst + e);
        int pos = atomicAdd(cursor + d, 1);
        csr[pos] = make_int2(__ldg(src + e), __float_as_int(__ldg(w + e)));
    }
}

// ---------------------------------------------------------------------------
// GEMM1 via mma.sync bf16 3-split: sup1[128-tile,64] = X[tile,256] @ W1
// Epilogue writes fp16 (half2).
// ---------------------------------------------------------------------------
#define OFF_AH 0
#define OFF_AL 16384
#define OFF_BH 32768
#define OFF_BL 40960

__global__ void __launch_bounds__(128)
gemm1_mma_kernel(const float* __restrict__ x,
                 const __nv_bfloat16* __restrict__ w1t_hi,
                 const __nv_bfloat16* __restrict__ w1t_lo,
                 __half* __restrict__ out, int nrows) {
    __shared__ __align__(16) char smem[49152];
    const uint32_t sb = smem_u32(smem);
    const int tid = threadIdx.x;
    const int wid = tid >> 5;
    const int lane = tid & 31;
    const int rowBase = blockIdx.x * 128;

    float acc[2][8][4];
#pragma unroll
    for (int mt = 0; mt < 2; mt++)
#pragma unroll
        for (int nt = 0; nt < 8; nt++)
#pragma unroll
            for (int j = 0; j < 4; j++) acc[mt][nt][j] = 0.f;

    for (int kc = 0; kc < NFEAT; kc += 64) {
#pragma unroll
        for (int it = 0; it < 16; it++) {
            int i = tid + it * 128;
            int row = i >> 4;
            int c4 = (i & 15) * 4;
            float4 v = make_float4(0.f, 0.f, 0.f, 0.f);
            int grow = rowBase + row;
            if (grow < nrows)
                v = *(const float4*)(x + (size_t)grow * NFEAT + kc + c4);
            __nv_bfloat162 h01 = __floats2bfloat162_rn(v.x, v.y);
            __nv_bfloat162 h23 = __floats2bfloat162_rn(v.z, v.w);
            __nv_bfloat162 l01 = __floats2bfloat162_rn(v.x - __bfloat162float(h01.x),
                                                       v.y - __bfloat162float(h01.y));
            __nv_bfloat162 l23 = __floats2bfloat162_rn(v.z - __bfloat162float(h23.x),
                                                       v.w - __bfloat162float(h23.y));
            uint32_t off = SWZ((uint32_t)(row * 128 + c4 * 2));
            uint2 uh, ul;
            uh.x = *(uint32_t*)&h01; uh.y = *(uint32_t*)&h23;
            ul.x = *(uint32_t*)&l01; ul.y = *(uint32_t*)&l23;
            *(uint2*)(smem + OFF_AH + off) = uh;
            *(uint2*)(smem + OFF_AL + off) = ul;
        }
#pragma unroll
        for (int it = 0; it < 4; it++) {
            int i = tid + it * 128;
            int n = i >> 3;
            int kb = (i & 7) * 16;
            uint4 vh = *(const uint4*)((const char*)w1t_hi + (size_t)n * 512 + kc * 2 + kb);
            uint4 vl = *(const uint4*)((const char*)w1t_lo + (size_t)n * 512 + kc * 2 + kb);
            uint32_t off = SWZ((uint32_t)(n * 128 + kb));
            *(uint4*)(smem + OFF_BH + off) = vh;
            *(uint4*)(smem + OFF_BL + off) = vl;
        }
        __syncthreads();

#pragma unroll
        for (int ks = 0; ks < 4; ks++) {
            uint32_t ah[2][4], al[2][4];
#pragma unroll
            for (int mt = 0; mt < 2; mt++) {
                int r = wid * 32 + mt * 16 + (lane & 15);
                uint32_t off = SWZ((uint32_t)(r * 128 + ks * 32 + (lane >> 4) * 16));
                ldm_x4(ah[mt], sb + OFF_AH + off);
                ldm_x4(al[mt], sb + OFF_AL + off);
            }
            uint32_t bh[4][4], bl[4][4];
#pragma unroll
            for (int np = 0; np < 4; np++) {
                int n = np * 16 + ((lane >> 4) & 1) * 8 + (lane & 7);
                int kb = ((lane >> 3) & 1) * 16;
                uint32_t off = SWZ((uint32_t)(n * 128 + ks * 32 + kb));
                ldm_x4(bh[np], sb + OFF_BH + off);
                ldm_x4(bl[np], sb + OFF_BL + off);
            }
#pragma unroll
            for (int mt = 0; mt < 2; mt++)
#pragma unroll
                for (int np = 0; np < 4; np++) {
                    mma_bf16(acc[mt][np * 2 + 0], ah[mt], bh[np][0], bh[np][1]);
                    mma_bf16(acc[mt][np * 2 + 1], ah[mt], bh[np][2], bh[np][3]);
                    mma_bf16(acc[mt][np * 2 + 0], ah[mt], bl[np][0], bl[np][1]);
                    mma_bf16(acc[mt][np * 2 + 1], ah[mt], bl[np][2], bl[np][3]);
                    mma_bf16(acc[mt][np * 2 + 0], al[mt], bh[np][0], bh[np][1]);
                    mma_bf16(acc[mt][np * 2 + 1], al[mt], bh[np][2], bh[np][3]);
                }
        }
        __syncthreads();
    }

#pragma unroll
    for (int mt = 0; mt < 2; mt++) {
        int row0 = rowBase + wid * 32 + mt * 16 + (lane >> 2);
        int row1 = row0 + 8;
#pragma unroll
        for (int nt = 0; nt < 8; nt++) {
            int col = nt * 8 + (lane & 3) * 2;
            if (row0 < nrows)
                *(__half2*)(out + (size_t)row0 * NHID + col) =
                    __floats2half2_rn(acc[mt][nt][0], acc[mt][nt][1]);
            if (row1 < nrows)
                *(__half2*)(out + (size_t)row1 * NHID + col) =
                    __floats2half2_rn(acc[mt][nt][2], acc[mt][nt][3]);
        }
    }
}

// ---------------------------------------------------------------------------
// SpMM F=64 gather (fp16 source): one warp per dst node, fp32 accumulation.
// ---------------------------------------------------------------------------
__global__ void spmm64_gather_kernel(const int2* __restrict__ csr,
                                     const int* __restrict__ off,
                                     const int* __restrict__ deg,
                                     const __half* __restrict__ sup,
                                     float* __restrict__ out, int n) {
    int node = (blockIdx.x * blockDim.x + threadIdx.x) >> 5;
    int lane = threadIdx.x & 31;
    if (node >= n) return;

    int start = __ldg(off + node);
    int d = __ldg(deg + node);
    float2 acc = make_float2(0.f, 0.f);

    int nfull = d & ~31;
    for (int i = 0; i < nfull; i += 32) {
        int2 my = __ldg(csr + start + i + lane);
#pragma unroll 8
        for (int j = 0; j < 32; j++) {
            int s = __shfl_sync(0xffffffffu, my.x, j);
            float wj = __int_as_float(__shfl_sync(0xffffffffu, my.y, j));
            float2 v = __half22float2(*(const __half2*)(sup + (size_t)s * NHID + lane * 2));
            acc.x += wj * v.x;
            acc.y += wj * v.y;
        }
    }
    int rem = d - nfull;
    if (rem) {
        int2 my = (lane < rem) ? __ldg(csr + start + nfull + lane) : make_int2(0, 0);
        for (int j = 0; j < rem; j++) {
            int s = __shfl_sync(0xffffffffu, my.x, j);
            float wj = __int_as_float(__shfl_sync(0xffffffffu, my.y, j));
            float2 v = __half22float2(*(const __half2*)(sup + (size_t)s * NHID + lane * 2));
            acc.x += wj * v.x;
            acc.y += wj * v.y;
        }
    }
    *(float2*)(out + (size_t)node * NHID + lane * 2) = acc;
}

// ---------------------------------------------------------------------------
// GEMM2 fused with bias+ReLU: sup2[n,16] = relu(hacc[n,:]+b1) @ W2[64,16]
// ---------------------------------------------------------------------------
__global__ void gemm2_relu_kernel(const float* __restrict__ hacc,
                                  const float* __restrict__ b1,
                                  const float* __restrict__ W2,
                                  __half* __restrict__ sup2, int n) {
    __shared__ float hs[16][64];
    __shared__ float w2s[64 * 16];

    const int tid = threadIdx.x;
    const int nodeBase = blockIdx.x * 16;

    ((float4*)w2s)[tid] = ((const float4*)W2)[tid];

    {
        int node = tid >> 4;
        int k4 = (tid & 15) * 4;
        float4 v = *(const float4*)(hacc + (size_t)(nodeBase + node) * NHID + k4);
        float4 b = *(const float4*)(b1 + k4);
        v.x = fmaxf(v.x + b.x, 0.f);
        v.y = fmaxf(v.y + b.y, 0.f);
        v.z = fmaxf(v.z + b.z, 0.f);
        v.w = fmaxf(v.w + b.w, 0.f);
        *(float4*)&hs[node][k4] = v;
    }
    __syncthreads();

    int node = tid >> 4;
    int c = tid & 15;
    float acc = 0.f;
#pragma unroll
    for (int k = 0; k < NHID; k++)
        acc += hs[node][k] * w2s[k * NCLASS + c];

    sup2[(size_t)(nodeBase + node) * NCLASS + c] = __float2half(acc);
}

// ---------------------------------------------------------------------------
// SpMM F=16 gather (fp16 source) + bias + log_softmax. Half-warp per node.
// ---------------------------------------------------------------------------
__global__ void spmm16_lsm_kernel(const int2* __restrict__ csr,
                                  const int* __restrict__ off,
                                  const int* __restrict__ deg,
                                  const __half* __restrict__ sup,
                                  const float* __restrict__ b2,
                                  float* __restrict__ out, int n) {
    int gtid = blockIdx.x * blockDim.x + threadIdx.x;
    int node = gtid >> 4;
    int l16 = threadIdx.x & 15;
    unsigned segmask = 0xFFFFu << (threadIdx.x & 16);
    if (node >= n) return;

    int start = __ldg(off + node);
    int d = __ldg(deg + node);
    float acc = 0.f;

    int nfull = d & ~15;
    for (int i = 0; i < nfull; i += 16) {
        int2 my = __ldg(csr + start + i + l16);
#pragma unroll 8
        for (int j = 0; j < 16; j++) {
            int s = __shfl_sync(segmask, my.x, j, 16);
            float wj = __int_as_float(__shfl_sync(segmask, my.y, j, 16));
            acc += wj * __half2float(__ldg(sup + (size_t)s * NCLASS + l16));
        }
    }
    int rem = d - nfull;
    if (rem) {
        int2 my = (l16 < rem) ? __ldg(csr + start + nfull + l16) : make_int2(0, 0);
        for (int j = 0; j < rem; j++) {
            int s = __shfl_sync(segmask, my.x, j, 16);
            float wj = __int_as_float(__shfl_sync(segmask, my.y, j, 16));
            acc += wj * __half2float(__ldg(sup + (size_t)s * NCLASS + l16));
        }
    }

    acc += __ldg(b2 + l16);

    float m = acc;
#pragma unroll
    for (int o = 8; o >= 1; o >>= 1)
        m = fmaxf(m, __shfl_xor_sync(segmask, m, o, 16));
    float ex = expf(acc - m);
    float s = ex;
#pragma unroll
    for (int o = 8; o >= 1; o >>= 1)
        s += __shfl_xor_sync(segmask, s, o, 16);
    float lse = m + logf(s);

    out[(size_t)node * NCLASS + l16] = acc - lse;
}

extern "C" void kernel_launch(void* const* d_in, const int* in_sizes, int n_in,
                              void* d_out, int out_size) {
    const float* x   = (const float*)d_in[0];
    const float* W1  = (const float*)d_in[1];
    const float* b1  = (const float*)d_in[2];
    const float* W2  = (const float*)d_in[3];
    const float* b2  = (const float*)d_in[4];
    const int* esrc  = (const int*)d_in[5];
    const int* edst  = (const int*)d_in[6];
    const float* ew  = (const float*)d_in[7];

    const int E = in_sizes[5];
    const int n = out_size / NCLASS;  // 50000
    float* out = (float*)d_out;

    float* hacc;
    __half *sup1, *sup2;
    int *deg, *off, *cursor, *bagg, *bflag;
    int2* csr;
    __nv_bfloat16 *w1h, *w1l;
    cudaGetSymbolAddress((void**)&sup1, g_sup1);
    cudaGetSymbolAddress((void**)&hacc, g_hacc);
    cudaGetSymbolAddress((void**)&sup2, g_sup2);
    cudaGetSymbolAddress((void**)&deg, g_deg);
    cudaGetSymbolAddress((void**)&off, g_off);
    cudaGetSymbolAddress((void**)&cursor, g_cursor);
    cudaGetSymbolAddress((void**)&bagg, g_bagg);
    cudaGetSymbolAddress((void**)&bflag, g_bflag);
    cudaGetSymbolAddress((void**)&csr, g_csr);
    cudaGetSymbolAddress((void**)&w1h, g_w1t_hi);
    cudaGetSymbolAddress((void**)&w1l, g_w1t_lo);

    cudaMemsetAsync(deg, 0, (size_t)n * sizeof(int));
    cudaMemsetAsync(bflag, 0, NBLK * sizeof(int));

    // 1. histogram + W1 prep
    histprep_kernel<<<1184, 256>>>(edst, deg, W1, w1h, w1l, E);
    // 2. single-pass scan (off + cursor)
    scan_fused_kernel<<<NBLK, SCAN_BLK>>>(deg, off, cursor, bagg, bflag, n);
    // 3. CSR scatter
    scatter_kernel<<<1184, 256>>>(esrc, edst, ew, cursor, csr, E);
    // 4. dense layer-1 transform (captured by ncu)
    gemm1_mma_kernel<<<(n + 127) / 128, 128>>>(x, w1h, w1l, sup1, n);
    // 5. layer-1 aggregate
    spmm64_gather_kernel<<<(n * 32 + 255) / 256, 256>>>(csr, off, deg, sup1, hacc, n);
    // 6. layer-2 dense + ReLU
    gemm2_relu_kernel<<<n / 16, 256>>>(hacc, b1, W2, sup2, n);
    // 7. layer-2 aggregate + bias + log_softmax
    spmm16_lsm_kernel<<<(n * 16 + 255) / 256, 256>>>(csr, off, deg, sup2, b2, out, n);
}

// round 14
// speedup vs baseline: 1.0696x; 1.0696x over previous
#include <cuda_runtime.h>
#include <cuda_fp16.h>
#include <cstdint>

#define N_NODES 50000
#define NFEAT 256
#define NHID 64
#define NCLASS 16
#define N_EDGES 1600000
#define SCAN_BLK 1024
#define NBLK ((N_NODES + SCAN_BLK - 1) / SCAN_BLK)

// Scratch (no dynamic allocation allowed)
__device__ __half g_sup1[N_NODES * NHID];   // x @ W1   (fp16)
__device__ float  g_hacc[N_NODES * NHID];   // spmm1 result (fp32)
__device__ __half g_sup2[N_NODES * NCLASS]; // relu(h) @ W2 (fp16)
__device__ int   g_deg[N_NODES];
__device__ int   g_off[N_NODES];
__device__ int   g_cursor[N_NODES];
__device__ int   g_bsum[NBLK];
__device__ int2  g_csr[N_EDGES];            // packed (src, weight-bits), sorted by dst
__device__ __half g_w1t[NHID * NFEAT];      // W1^T fp16  [n][k]

// ============================ helpers ======================================
__device__ __forceinline__ uint32_t smem_u32(const void* p) {
    uint32_t a;
    asm("{ .reg .u64 t; cvta.to.shared.u64 t, %1; cvt.u32.u64 %0, t; }"
        : "=r"(a) : "l"(p));
    return a;
}

__device__ __forceinline__ void ldm_x4(uint32_t* r, uint32_t addr) {
    asm volatile("ldmatrix.sync.aligned.m8n8.x4.shared.b16 {%0,%1,%2,%3}, [%4];"
                 : "=r"(r[0]), "=r"(r[1]), "=r"(r[2]), "=r"(r[3]) : "r"(addr));
}

__device__ __forceinline__ void mma_f16(float* d, const uint32_t* a,
                                        uint32_t b0, uint32_t b1) {
    asm volatile("mma.sync.aligned.m16n8k16.row.col.f32.f16.f16.f32 "
                 "{%0,%1,%2,%3}, {%4,%5,%6,%7}, {%8,%9}, {%0,%1,%2,%3};"
                 : "+f"(d[0]), "+f"(d[1]), "+f"(d[2]), "+f"(d[3])
                 : "r"(a[0]), "r"(a[1]), "r"(a[2]), "r"(a[3]), "r"(b0), "r"(b1));
}

#define SWZ(off) ((off) ^ (((off) >> 3) & 0x70))

// ---------------------------------------------------------------------------
// W1 prep: transpose [256,64] -> [64,256], fp16
// ---------------------------------------------------------------------------
__global__ void prep_w1_kernel(const float* __restrict__ W1,
                               __half* __restrict__ w1t) {
    int i = blockIdx.x * blockDim.x + threadIdx.x;
    if (i >= NHID * NFEAT) return;
    int n = i >> 8, k = i & 255;
    w1t[i] = __float2half(__ldg(W1 + k * NHID + n));
}

// ---------------------------------------------------------------------------
// GEMM1 via mma.sync fp16 2-term split: sup1[128-tile,64] = X[tile,256] @ W1
// x -> fp16 hi+lo (residual ~2^-22); W1 single fp16.
// smem: AH(16K) AL(16K) B(8K) = 40KB, 128B rows + XOR swizzle.
// ---------------------------------------------------------------------------
#define OFF_AH 0
#define OFF_AL 16384
#define OFF_B  32768

__global__ void __launch_bounds__(128)
gemm1_mma_kernel(const float* __restrict__ x,
                 const __half* __restrict__ w1t,
                 __half* __restrict__ out, int nrows) {
    __shared__ __align__(16) char smem[40960];
    const uint32_t sb = smem_u32(smem);
    const int tid = threadIdx.x;
    const int wid = tid >> 5;
    const int lane = tid & 31;
    const int rowBase = blockIdx.x * 128;

    float acc[2][8][4];
#pragma unroll
    for (int mt = 0; mt < 2; mt++)
#pragma unroll
        for (int nt = 0; nt < 8; nt++)
#pragma unroll
            for (int j = 0; j < 4; j++) acc[mt][nt][j] = 0.f;

    for (int kc = 0; kc < NFEAT; kc += 64) {
        // A chunk: 128 rows x 64 fp32 -> fp16 hi/lo, swizzled 128B rows
#pragma unroll
        for (int it = 0; it < 16; it++) {
            int i = tid + it * 128;
            int row = i >> 4;
            int c4 = (i & 15) * 4;
            float4 v = make_float4(0.f, 0.f, 0.f, 0.f);
            int grow = rowBase + row;
            if (grow < nrows)
                v = *(const float4*)(x + (size_t)grow * NFEAT + kc + c4);
            __half2 h01 = __floats2half2_rn(v.x, v.y);
            __half2 h23 = __floats2half2_rn(v.z, v.w);
            __half2 l01 = __floats2half2_rn(v.x - __half2float(h01.x),
                                            v.y - __half2float(h01.y));
            __half2 l23 = __floats2half2_rn(v.z - __half2float(h23.x),
                                            v.w - __half2float(h23.y));
            uint32_t off = SWZ((uint32_t)(row * 128 + c4 * 2));
            uint2 uh, ul;
            uh.x = *(uint32_t*)&h01; uh.y = *(uint32_t*)&h23;
            ul.x = *(uint32_t*)&l01; ul.y = *(uint32_t*)&l23;
            *(uint2*)(smem + OFF_AH + off) = uh;
            *(uint2*)(smem + OFF_AL + off) = ul;
        }
        // B chunk: W1^T rows n=0..63, cols kc..kc+63 (128B per row)
#pragma unroll
        for (int it = 0; it < 4; it++) {
            int i = tid + it * 128;
            int n = i >> 3;
            int kb = (i & 7) * 16;
            uint4 vb = *(const uint4*)((const char*)w1t + (size_t)n * 512 + kc * 2 + kb);
            uint32_t off = SWZ((uint32_t)(n * 128 + kb));
            *(uint4*)(smem + OFF_B + off) = vb;
        }
        __syncthreads();

#pragma unroll
        for (int ks = 0; ks < 4; ks++) {
            uint32_t ah[2][4], al[2][4];
#pragma unroll
            for (int mt = 0; mt < 2; mt++) {
                int r = wid * 32 + mt * 16 + (lane & 15);
                uint32_t off = SWZ((uint32_t)(r * 128 + ks * 32 + (lane >> 4) * 16));
                ldm_x4(ah[mt], sb + OFF_AH + off);
                ldm_x4(al[mt], sb + OFF_AL + off);
            }
            uint32_t b[4][4];
#pragma unroll
            for (int np = 0; np < 4; np++) {
                int n = np * 16 + ((lane >> 4) & 1) * 8 + (lane & 7);
                int kb = ((lane >> 3) & 1) * 16;
                uint32_t off = SWZ((uint32_t)(n * 128 + ks * 32 + kb));
                ldm_x4(b[np], sb + OFF_B + off);
            }
#pragma unroll
            for (int mt = 0; mt < 2; mt++)
#pragma unroll
                for (int np = 0; np < 4; np++) {
                    mma_f16(acc[mt][np * 2 + 0], ah[mt], b[np][0], b[np][1]);
                    mma_f16(acc[mt][np * 2 + 1], ah[mt], b[np][2], b[np][3]);
                    mma_f16(acc[mt][np * 2 + 0], al[mt], b[np][0], b[np][1]);
                    mma_f16(acc[mt][np * 2 + 1], al[mt], b[np][2], b[np][3]);
                }
        }
        __syncthreads();
    }

    // Epilogue: write fp16 pairs
#pragma unroll
    for (int mt = 0; mt < 2; mt++) {
        int row0 = rowBase + wid * 32 + mt * 16 + (lane >> 2);
        int row1 = row0 + 8;
#pragma unroll
        for (int nt = 0; nt < 8; nt++) {
            int col = nt * 8 + (lane & 3) * 2;
            if (row0 < nrows)
                *(__half2*)(out + (size_t)row0 * NHID + col) =
                    __floats2half2_rn(acc[mt][nt][0], acc[mt][nt][1]);
            if (row1 < nrows)
                *(__half2*)(out + (size_t)row1 * NHID + col) =
                    __floats2half2_rn(acc[mt][nt][2], acc[mt][nt][3]);
        }
    }
}

// ---------------------------------------------------------------------------
// CSR build
// ---------------------------------------------------------------------------
__global__ void histogram_kernel(const int* __restrict__ dst, int* __restrict__ deg, int E) {
    int i = blockIdx.x * blockDim.x + threadIdx.x;
    int stride = gridDim.x * blockDim.x;
    for (int e = i; e < E; e += stride)
        atomicAdd(deg + __ldg(dst + e), 1);
}

__global__ void scan_block_kernel(const int* __restrict__ deg, int* __restrict__ off,
                                  int* __restrict__ bsum, int n) {
    __shared__ int warp_sums[32];
    int i = blockIdx.x * SCAN_BLK + threadIdx.x;
    int v = (i < n) ? deg[i] : 0;
    int lane = threadIdx.x & 31, wid = threadIdx.x >> 5;

    int incl = v;
#pragma unroll
    for (int o = 1; o < 32; o <<= 1) {
        int t = __shfl_up_sync(0xffffffffu, incl, o);
        if (lane >= o) incl += t;
    }
    if (lane == 31) warp_sums[wid] = incl;
    __syncthreads();
    if (wid == 0) {
        int s = warp_sums[lane];
#pragma unroll
        for (int o = 1; o < 32; o <<= 1) {
            int t = __shfl_up_sync(0xffffffffu, s, o);
            if (lane >= o) s += t;
        }
        warp_sums[lane] = s;
    }
    __syncthreads();
    int wpre = (wid == 0) ? 0 : warp_sums[wid - 1];
    if (i < n) off[i] = wpre + incl - v;
    if (threadIdx.x == SCAN_BLK - 1) bsum[blockIdx.x] = wpre + incl;
}

__global__ void scan_bsum_kernel(int* __restrict__ bsum, int nblk) {
    int t = threadIdx.x;
    int lane = t & 31, wid = t >> 5;
    int v = (t < nblk) ? bsum[t] : 0;
    int incl = v;
#pragma unroll
    for (int o = 1; o < 32; o <<= 1) {
        int u = __shfl_up_sync(0xffffffffu, incl, o);
        if (lane >= o) incl += u;
    }
    __shared__ int w0tot;
    if (wid == 0 && lane == 31) w0tot = incl;
    __syncthreads();
    int ex = incl - v + (wid ? w0tot : 0);
    if (t < nblk) bsum[t] = ex;
}

__global__ void scan_fixup_kernel(int* __restrict__ off, int* __restrict__ cursor,
                                  const int* __restrict__ bsum, int n) {
    int i = blockIdx.x * blockDim.x + threadIdx.x;
    if (i < n) {
        int o = off[i] + bsum[i >> 10];
        off[i] = o;
        cursor[i] = o;
    }
}

__global__ void scatter_kernel(const int* __restrict__ src, const int* __restrict__ dst,
                               const float* __restrict__ w, int* __restrict__ cursor,
                               int2* __restrict__ csr, int E) {
    int i = blockIdx.x * blockDim.x + threadIdx.x;
    int stride = gridDim.x * blockDim.x;
    for (int e = i; e < E; e += stride) {
        int d = __ldg(dst + e);
        int pos = atomicAdd(cursor + d, 1);
        csr[pos] = make_int2(__ldg(src + e), __float_as_int(__ldg(w + e)));
    }
}

// ---------------------------------------------------------------------------
// SpMM F=64 gather (fp16 source): one warp per dst node, fp32 accumulation.
// ---------------------------------------------------------------------------
__global__ void spmm64_gather_kernel(const int2* __restrict__ csr,
                                     const int* __restrict__ off,
                                     const int* __restrict__ deg,
                                     const __half* __restrict__ sup,
                                     float* __restrict__ out, int n) {
    int node = (blockIdx.x * blockDim.x + threadIdx.x) >> 5;
    int lane = threadIdx.x & 31;
    if (node >= n) return;

    int start = __ldg(off + node);
    int d = __ldg(deg + node);
    float2 acc = make_float2(0.f, 0.f);

    int nfull = d & ~31;
    for (int i = 0; i < nfull; i += 32) {
        int2 my = __ldg(csr + start + i + lane);
#pragma unroll 8
        for (int j = 0; j < 32; j++) {
            int s = __shfl_sync(0xffffffffu, my.x, j);
            float wj = __int_as_float(__shfl_sync(0xffffffffu, my.y, j));
            float2 v = __half22float2(*(const __half2*)(sup + (size_t)s * NHID + lane * 2));
            acc.x += wj * v.x;
            acc.y += wj * v.y;
        }
    }
    int rem = d - nfull;
    if (rem) {
        int2 my = (lane < rem) ? __ldg(csr + start + nfull + lane) : make_int2(0, 0);
        for (int j = 0; j < rem; j++) {
            int s = __shfl_sync(0xffffffffu, my.x, j);
            float wj = __int_as_float(__shfl_sync(0xffffffffu, my.y, j));
            float2 v = __half22float2(*(const __half2*)(sup + (size_t)s * NHID + lane * 2));
            acc.x += wj * v.x;
            acc.y += wj * v.y;
        }
    }
    *(float2*)(out + (size_t)node * NHID + lane * 2) = acc;
}

// ---------------------------------------------------------------------------
// GEMM2 fused with bias+ReLU: sup2[n,16] = relu(hacc[n,:]+b1) @ W2[64,16]
// ---------------------------------------------------------------------------
__global__ void gemm2_relu_kernel(const float* __restrict__ hacc,
                                  const float* __restrict__ b1,
                                  const float* __restrict__ W2,
                                  __half* __restrict__ sup2, int n) {
    __shared__ float hs[16][64];
    __shared__ float w2s[64 * 16];

    const int tid = threadIdx.x;
    const int nodeBase = blockIdx.x * 16;

    ((float4*)w2s)[tid] = ((const float4*)W2)[tid];

    {
        int node = tid >> 4;
        int k4 = (tid & 15) * 4;
        float4 v = *(const float4*)(hacc + (size_t)(nodeBase + node) * NHID + k4);
        float4 b = *(const float4*)(b1 + k4);
        v.x = fmaxf(v.x + b.x, 0.f);
        v.y = fmaxf(v.y + b.y, 0.f);
        v.z = fmaxf(v.z + b.z, 0.f);
        v.w = fmaxf(v.w + b.w, 0.f);
        *(float4*)&hs[node][k4] = v;
    }
    __syncthreads();

    int node = tid >> 4;
    int c = tid & 15;
    float acc = 0.f;
#pragma unroll
    for (int k = 0; k < NHID; k++)
        acc += hs[node][k] * w2s[k * NCLASS + c];

    sup2[(size_t)(nodeBase + node) * NCLASS + c] = __float2half(acc);
}

// ---------------------------------------------------------------------------
// SpMM F=16 gather (fp16 source) + bias + log_softmax. Half-warp per node.
// ---------------------------------------------------------------------------
__global__ void spmm16_lsm_kernel(const int2* __restrict__ csr,
                                  const int* __restrict__ off,
                                  const int* __restrict__ deg,
                                  const __half* __restrict__ sup,
                                  const float* __restrict__ b2,
                                  float* __restrict__ out, int n) {
    int gtid = blockIdx.x * blockDim.x + threadIdx.x;
    int node = gtid >> 4;
    int l16 = threadIdx.x & 15;
    unsigned segmask = 0xFFFFu << (threadIdx.x & 16);
    if (node >= n) return;

    int start = __ldg(off + node);
    int d = __ldg(deg + node);
    float acc = 0.f;

    int nfull = d & ~15;
    for (int i = 0; i < nfull; i += 16) {
        int2 my = __ldg(csr + start + i + l16);
#pragma unroll 8
        for (int j = 0; j < 16; j++) {
            int s = __shfl_sync(segmask, my.x, j, 16);
            float wj = __int_as_float(__shfl_sync(segmask, my.y, j, 16));
            acc += wj * __half2float(__ldg(sup + (size_t)s * NCLASS + l16));
        }
    }
    int rem = d - nfull;
    if (rem) {
        int2 my = (l16 < rem) ? __ldg(csr + start + nfull + l16) : make_int2(0, 0);
        for (int j = 0; j < rem; j++) {
            int s = __shfl_sync(segmask, my.x, j, 16);
            float wj = __int_as_float(__shfl_sync(segmask, my.y, j, 16));
            acc += wj * __half2float(__ldg(sup + (size_t)s * NCLASS + l16));
        }
    }

    acc += __ldg(b2 + l16);

    float m = acc;
#pragma unroll
    for (int o = 8; o >= 1; o >>= 1)
        m = fmaxf(m, __shfl_xor_sync(segmask, m, o, 16));
    float ex = expf(acc - m);
    float s = ex;
#pragma unroll
    for (int o = 8; o >= 1; o >>= 1)
        s += __shfl_xor_sync(segmask, s, o, 16);
    float lse = m + logf(s);

    out[(size_t)node * NCLASS + l16] = acc - lse;
}

extern "C" void kernel_launch(void* const* d_in, const int* in_sizes, int n_in,
                              void* d_out, int out_size) {
    const float* x   = (const float*)d_in[0];
    const float* W1  = (const float*)d_in[1];
    const float* b1  = (const float*)d_in[2];
    const float* W2  = (const float*)d_in[3];
    const float* b2  = (const float*)d_in[4];
    const int* esrc  = (const int*)d_in[5];
    const int* edst  = (const int*)d_in[6];
    const float* ew  = (const float*)d_in[7];

    const int E = in_sizes[5];
    const int n = out_size / NCLASS;  // 50000
    float* out = (float*)d_out;

    float* hacc;
    __half *sup1, *sup2, *w1t;
    int *deg, *off, *cursor, *bsum;
    int2* csr;
    cudaGetSymbolAddress((void**)&sup1, g_sup1);
    cudaGetSymbolAddress((void**)&hacc, g_hacc);
    cudaGetSymbolAddress((void**)&sup2, g_sup2);
    cudaGetSymbolAddress((void**)&deg, g_deg);
    cudaGetSymbolAddress((void**)&off, g_off);
    cudaGetSymbolAddress((void**)&cursor, g_cursor);
    cudaGetSymbolAddress((void**)&bsum, g_bsum);
    cudaGetSymbolAddress((void**)&csr, g_csr);
    cudaGetSymbolAddress((void**)&w1t, g_w1t);

    // Dense layer-1 transform on tensor pipe (fp16 2-term split), fp16 out
    prep_w1_kernel<<<(NHID * NFEAT + 255) / 256, 256>>>(W1, w1t);
    gemm1_mma_kernel<<<(n + 127) / 128, 128>>>(x, w1t, sup1, n);

    // CSR build (by dst)
    cudaMemsetAsync(deg, 0, (size_t)n * sizeof(int));
    histogram_kernel<<<1184, 256>>>(edst, deg, E);
    scan_block_kernel<<<NBLK, SCAN_BLK>>>(deg, off, bsum, n);
    scan_bsum_kernel<<<1, 64>>>(bsum, NBLK);
    scan_fixup_kernel<<<(n + 255) / 256, 256>>>(off, cursor, bsum, n);
    scatter_kernel<<<1184, 256>>>(esrc, edst, ew, cursor, csr, E);

    // Layer 1 aggregate (fp16 gather, fp32 accumulate)
    spmm64_gather_kernel<<<(n * 32 + 255) / 256, 256>>>(csr, off, deg, sup1, hacc, n);

    // Layer 2
    gemm2_relu_kernel<<<n / 16, 256>>>(hacc, b1, W2, sup2, n);
    spmm16_lsm_kernel<<<(n * 16 + 255) / 256, 256>>>(csr, off, deg, sup2, b2, out, n);
}

// round 16
// speedup vs baseline: 1.1371x; 1.0631x over previous
#include <cuda_runtime.h>
#include <cuda_fp16.h>
#include <cstdint>

#define N_NODES 50000
#define NFEAT 256
#define NHID 64
#define NCLASS 16
#define N_EDGES 1600000
#define SCAN_BLK 1024
#define NBLK ((N_NODES + SCAN_BLK - 1) / SCAN_BLK)

// Scratch (no dynamic allocation allowed)
__device__ __half g_sup1[N_NODES * NHID];   // x @ W1   (fp16)
__device__ __half g_hacc[N_NODES * NHID];   // relu(spmm1 + b1)  (fp16)
__device__ __half g_sup2[N_NODES * NCLASS]; // relu-h @ W2 (fp16)
__device__ int   g_deg[N_NODES];
__device__ int   g_off[N_NODES];
__device__ int   g_cursor[N_NODES];
__device__ int   g_bsum[NBLK];
__device__ int2  g_csr[N_EDGES];            // packed (src, weight-bits), sorted by dst
__device__ __half g_w1t[NHID * NFEAT];      // W1^T fp16  [n][k]

// ============================ helpers ======================================
__device__ __forceinline__ uint32_t smem_u32(const void* p) {
    uint32_t a;
    asm("{ .reg .u64 t; cvta.to.shared.u64 t, %1; cvt.u32.u64 %0, t; }"
        : "=r"(a) : "l"(p));
    return a;
}

__device__ __forceinline__ void ldm_x4(uint32_t* r, uint32_t addr) {
    asm volatile("ldmatrix.sync.aligned.m8n8.x4.shared.b16 {%0,%1,%2,%3}, [%4];"
                 : "=r"(r[0]), "=r"(r[1]), "=r"(r[2]), "=r"(r[3]) : "r"(addr));
}

__device__ __forceinline__ void mma_f16(float* d, const uint32_t* a,
                                        uint32_t b0, uint32_t b1) {
    asm volatile("mma.sync.aligned.m16n8k16.row.col.f32.f16.f16.f32 "
                 "{%0,%1,%2,%3}, {%4,%5,%6,%7}, {%8,%9}, {%0,%1,%2,%3};"
                 : "+f"(d[0]), "+f"(d[1]), "+f"(d[2]), "+f"(d[3])
                 : "r"(a[0]), "r"(a[1]), "r"(a[2]), "r"(a[3]), "r"(b0), "r"(b1));
}

#define SWZ(off) ((off) ^ (((off) >> 3) & 0x70))

// ---------------------------------------------------------------------------
// W1 prep: transpose [256,64] -> [64,256], fp16
// ---------------------------------------------------------------------------
__global__ void prep_w1_kernel(const float* __restrict__ W1,
                               __half* __restrict__ w1t) {
    int i = blockIdx.x * blockDim.x + threadIdx.x;
    if (i >= NHID * NFEAT) return;
    int n = i >> 8, k = i & 255;
    w1t[i] = __float2half(__ldg(W1 + k * NHID + n));
}

// ---------------------------------------------------------------------------
// GEMM1 via mma.sync fp16 2-term split: sup1[128-tile,64] = X[tile,256] @ W1
// x -> fp16 hi+lo (residual ~2^-22); W1 single fp16.
// __launch_bounds__(128, 3): cap regs so 3 CTAs/SM stay resident (DRAM duty).
// ---------------------------------------------------------------------------
#define OFF_AH 0
#define OFF_AL 16384
#define OFF_B  32768

__global__ void __launch_bounds__(128, 3)
gemm1_mma_kernel(const float* __restrict__ x,
                 const __half* __restrict__ w1t,
                 __half* __restrict__ out, int nrows) {
    __shared__ __align__(16) char smem[40960];
    const uint32_t sb = smem_u32(smem);
    const int tid = threadIdx.x;
    const int wid = tid >> 5;
    const int lane = tid & 31;
    const int rowBase = blockIdx.x * 128;

    float acc[2][8][4];
#pragma unroll
    for (int mt = 0; mt < 2; mt++)
#pragma unroll
        for (int nt = 0; nt < 8; nt++)
#pragma unroll
            for (int j = 0; j < 4; j++) acc[mt][nt][j] = 0.f;

    for (int kc = 0; kc < NFEAT; kc += 64) {
        // A chunk: 128 rows x 64 fp32 -> fp16 hi/lo, swizzled 128B rows
#pragma unroll
        for (int it = 0; it < 16; it++) {
            int i = tid + it * 128;
            int row = i >> 4;
            int c4 = (i & 15) * 4;
            float4 v = make_float4(0.f, 0.f, 0.f, 0.f);
            int grow = rowBase + row;
            if (grow < nrows)
                v = *(const float4*)(x + (size_t)grow * NFEAT + kc + c4);
            __half2 h01 = __floats2half2_rn(v.x, v.y);
            __half2 h23 = __floats2half2_rn(v.z, v.w);
            __half2 l01 = __floats2half2_rn(v.x - __half2float(h01.x),
                                            v.y - __half2float(h01.y));
            __half2 l23 = __floats2half2_rn(v.z - __half2float(h23.x),
                                            v.w - __half2float(h23.y));
            uint32_t off = SWZ((uint32_t)(row * 128 + c4 * 2));
            uint2 uh, ul;
            uh.x = *(uint32_t*)&h01; uh.y = *(uint32_t*)&h23;
            ul.x = *(uint32_t*)&l01; ul.y = *(uint32_t*)&l23;
            *(uint2*)(smem + OFF_AH + off) = uh;
            *(uint2*)(smem + OFF_AL + off) = ul;
        }
        // B chunk: W1^T rows n=0..63, cols kc..kc+63 (128B per row)
#pragma unroll
        for (int it = 0; it < 4; it++) {
            int i = tid + it * 128;
            int n = i >> 3;
            int kb = (i & 7) * 16;
            uint4 vb = *(const uint4*)((const char*)w1t + (size_t)n * 512 + kc * 2 + kb);
            uint32_t off = SWZ((uint32_t)(n * 128 + kb));
            *(uint4*)(smem + OFF_B + off) = vb;
        }
        __syncthreads();

#pragma unroll
        for (int ks = 0; ks < 4; ks++) {
            uint32_t ah[2][4], al[2][4];
#pragma unroll
            for (int mt = 0; mt < 2; mt++) {
                int r = wid * 32 + mt * 16 + (lane & 15);
                uint32_t off = SWZ((uint32_t)(r * 128 + ks * 32 + (lane >> 4) * 16));
                ldm_x4(ah[mt], sb + OFF_AH + off);
                ldm_x4(al[mt], sb + OFF_AL + off);
            }
            uint32_t b[4][4];
#pragma unroll
            for (int np = 0; np < 4; np++) {
                int n = np * 16 + ((lane >> 4) & 1) * 8 + (lane & 7);
                int kb = ((lane >> 3) & 1) * 16;
                uint32_t off = SWZ((uint32_t)(n * 128 + ks * 32 + kb));
                ldm_x4(b[np], sb + OFF_B + off);
            }
#pragma unroll
            for (int mt = 0; mt < 2; mt++)
#pragma unroll
                for (int np = 0; np < 4; np++) {
                    mma_f16(acc[mt][np * 2 + 0], ah[mt], b[np][0], b[np][1]);
                    mma_f16(acc[mt][np * 2 + 1], ah[mt], b[np][2], b[np][3]);
                    mma_f16(acc[mt][np * 2 + 0], al[mt], b[np][0], b[np][1]);
                    mma_f16(acc[mt][np * 2 + 1], al[mt], b[np][2], b[np][3]);
                }
        }
        __syncthreads();
    }

    // Epilogue: write fp16 pairs
#pragma unroll
    for (int mt = 0; mt < 2; mt++) {
        int row0 = rowBase + wid * 32 + mt * 16 + (lane >> 2);
        int row1 = row0 + 8;
#pragma unroll
        for (int nt = 0; nt < 8; nt++) {
            int col = nt * 8 + (lane & 3) * 2;
            if (row0 < nrows)
                *(__half2*)(out + (size_t)row0 * NHID + col) =
                    __floats2half2_rn(acc[mt][nt][0], acc[mt][nt][1]);
            if (row1 < nrows)
                *(__half2*)(out + (size_t)row1 * NHID + col) =
                    __floats2half2_rn(acc[mt][nt][2], acc[mt][nt][3]);
        }
    }
}

// ---------------------------------------------------------------------------
// CSR build
// ---------------------------------------------------------------------------
__global__ void histogram_kernel(const int* __restrict__ dst, int* __restrict__ deg, int E) {
    int i = blockIdx.x * blockDim.x + threadIdx.x;
    int stride = gridDim.x * blockDim.x;
    for (int e = i; e < E; e += stride)
        atomicAdd(deg + __ldg(dst + e), 1);
}

__global__ void scan_block_kernel(const int* __restrict__ deg, int* __restrict__ off,
                                  int* __restrict__ bsum, int n) {
    __shared__ int warp_sums[32];
    int i = blockIdx.x * SCAN_BLK + threadIdx.x;
    int v = (i < n) ? deg[i] : 0;
    int lane = threadIdx.x & 31, wid = threadIdx.x >> 5;

    int incl = v;
#pragma unroll
    for (int o = 1; o < 32; o <<= 1) {
        int t = __shfl_up_sync(0xffffffffu, incl, o);
        if (lane >= o) incl += t;
    }
    if (lane == 31) warp_sums[wid] = incl;
    __syncthreads();
    if (wid == 0) {
        int s = warp_sums[lane];
#pragma unroll
        for (int o = 1; o < 32; o <<= 1) {
            int t = __shfl_up_sync(0xffffffffu, s, o);
            if (lane >= o) s += t;
        }
        warp_sums[lane] = s;
    }
    __syncthreads();
    int wpre = (wid == 0) ? 0 : warp_sums[wid - 1];
    if (i < n) off[i] = wpre + incl - v;
    if (threadIdx.x == SCAN_BLK - 1) bsum[blockIdx.x] = wpre + incl;
}

__global__ void scan_bsum_kernel(int* __restrict__ bsum, int nblk) {
    int t = threadIdx.x;
    int lane = t & 31, wid = t >> 5;
    int v = (t < nblk) ? bsum[t] : 0;
    int incl = v;
#pragma unroll
    for (int o = 1; o < 32; o <<= 1) {
        int u = __shfl_up_sync(0xffffffffu, incl, o);
        if (lane >= o) incl += u;
    }
    __shared__ int w0tot;
    if (wid == 0 && lane == 31) w0tot = incl;
    __syncthreads();
    int ex = incl - v + (wid ? w0tot : 0);
    if (t < nblk) bsum[t] = ex;
}

__global__ void scan_fixup_kernel(int* __restrict__ off, int* __restrict__ cursor,
                                  const int* __restrict__ bsum, int n) {
    int i = blockIdx.x * blockDim.x + threadIdx.x;
    if (i < n) {
        int o = off[i] + bsum[i >> 10];
        off[i] = o;
        cursor[i] = o;
    }
}

__global__ void scatter_kernel(const int* __restrict__ src, const int* __restrict__ dst,
                               const float* __restrict__ w, int* __restrict__ cursor,
                               int2* __restrict__ csr, int E) {
    int i = blockIdx.x * blockDim.x + threadIdx.x;
    int stride = gridDim.x * blockDim.x;
    for (int e = i; e < E; e += stride) {
        int d = __ldg(dst + e);
        int pos = atomicAdd(cursor + d, 1);
        csr[pos] = make_int2(__ldg(src + e), __float_as_int(__ldg(w + e)));
    }
}

// ---------------------------------------------------------------------------
// SpMM F=64 gather (fp16 source) + bias + ReLU fused; fp16 output.
// One warp per dst node, fp32 accumulation.
// ---------------------------------------------------------------------------
__global__ void spmm64_gather_kernel(const int2* __restrict__ csr,
                                     const int* __restrict__ off,
                                     const int* __restrict__ deg,
                                     const __half* __restrict__ sup,
                                     const float* __restrict__ b1,
                                     __half* __restrict__ out, int n) {
    int node = (blockIdx.x * blockDim.x + threadIdx.x) >> 5;
    int lane = threadIdx.x & 31;
    if (node >= n) return;

    int start = __ldg(off + node);
    int d = __ldg(deg + node);
    float2 acc = make_float2(0.f, 0.f);

    int nfull = d & ~31;
    for (int i = 0; i < nfull; i += 32) {
        int2 my = __ldg(csr + start + i + lane);
#pragma unroll 8
        for (int j = 0; j < 32; j++) {
            int s = __shfl_sync(0xffffffffu, my.x, j);
            float wj = __int_as_float(__shfl_sync(0xffffffffu, my.y, j));
            float2 v = __half22float2(*(const __half2*)(sup + (size_t)s * NHID + lane * 2));
            acc.x += wj * v.x;
            acc.y += wj * v.y;
        }
    }
    int rem = d - nfull;
    if (rem) {
        int2 my = (lane < rem) ? __ldg(csr + start + nfull + lane) : make_int2(0, 0);
        for (int j = 0; j < rem; j++) {
            int s = __shfl_sync(0xffffffffu, my.x, j);
            float wj = __int_as_float(__shfl_sync(0xffffffffu, my.y, j));
            float2 v = __half22float2(*(const __half2*)(sup + (size_t)s * NHID + lane * 2));
            acc.x += wj * v.x;
            acc.y += wj * v.y;
        }
    }

    // Fused bias + ReLU, fp16 store
    float2 b = *(const float2*)(b1 + lane * 2);
    float hx = fmaxf(acc.x + b.x, 0.f);
    float hy = fmaxf(acc.y + b.y, 0.f);
    *(__half2*)(out + (size_t)node * NHID + lane * 2) = __floats2half2_rn(hx, hy);
}

// ---------------------------------------------------------------------------
// GEMM2: sup2[n,16] = h[n,:] @ W2[64,16]   (h already biased+ReLUed, fp16)
// ---------------------------------------------------------------------------
__global__ void gemm2_kernel(const __half* __restrict__ hacc,
                             const float* __restrict__ W2,
                             __half* __restrict__ sup2, int n) {
    __shared__ float hs[16][64];
    __shared__ float w2s[64 * 16];

    const int tid = threadIdx.x;
    const int nodeBase = blockIdx.x * 16;

    ((float4*)w2s)[tid] = ((const float4*)W2)[tid];

    {
        int node = tid >> 4;
        int k4 = (tid & 15) * 4;
        const __half2* p = (const __half2*)(hacc + (size_t)(nodeBase + node) * NHID + k4);
        float2 v01 = __half22float2(p[0]);
        float2 v23 = __half22float2(p[1]);
        *(float4*)&hs[node][k4] = make_float4(v01.x, v01.y, v23.x, v23.y);
    }
    __syncthreads();

    int node = tid >> 4;
    int c = tid & 15;
    float acc = 0.f;
#pragma unroll
    for (int k = 0; k < NHID; k++)
        acc += hs[node][k] * w2s[k * NCLASS + c];

    sup2[(size_t)(nodeBase + node) * NCLASS + c] = __float2half(acc);
}

// ---------------------------------------------------------------------------
// SpMM F=16 gather (fp16 source) + bias + log_softmax. Half-warp per node.
// ---------------------------------------------------------------------------
__global__ void spmm16_lsm_kernel(const int2* __restrict__ csr,
                                  const int* __restrict__ off,
                                  const int* __restrict__ deg,
                                  const __half* __restrict__ sup,
                                  const float* __restrict__ b2,
                                  float* __restrict__ out, int n) {
    int gtid = blockIdx.x * blockDim.x + threadIdx.x;
    int node = gtid >> 4;
    int l16 = threadIdx.x & 15;
    unsigned segmask = 0xFFFFu << (threadIdx.x & 16);
    if (node >= n) return;

    int start = __ldg(off + node);
    int d = __ldg(deg + node);
    float acc = 0.f;

    int nfull = d & ~15;
    for (int i = 0; i < nfull; i += 16) {
        int2 my = __ldg(csr + start + i + l16);
#pragma unroll 8
        for (int j = 0; j < 16; j++) {
            int s = __shfl_sync(segmask, my.x, j, 16);
            float wj = __int_as_float(__shfl_sync(segmask, my.y, j, 16));
            acc += wj * __half2float(__ldg(sup + (size_t)s * NCLASS + l16));
        }
    }
    int rem = d - nfull;
    if (rem) {
        int2 my = (l16 < rem) ? __ldg(csr + start + nfull + l16) : make_int2(0, 0);
        for (int j = 0; j < rem; j++) {
            int s = __shfl_sync(segmask, my.x, j, 16);
            float wj = __int_as_float(__shfl_sync(segmask, my.y, j, 16));
            acc += wj * __half2float(__ldg(sup + (size_t)s * NCLASS + l16));
        }
    }

    acc += __ldg(b2 + l16);

    float m = acc;
#pragma unroll
    for (int o = 8; o >= 1; o >>= 1)
        m = fmaxf(m, __shfl_xor_sync(segmask, m, o, 16));
    float ex = expf(acc - m);
    float s = ex;
#pragma unroll
    for (int o = 8; o >= 1; o >>= 1)
        s += __shfl_xor_sync(segmask, s, o, 16);
    float lse = m + logf(s);

    out[(size_t)node * NCLASS + l16] = acc - lse;
}

extern "C" void kernel_launch(void* const* d_in, const int* in_sizes, int n_in,
                              void* d_out, int out_size) {
    const float* x   = (const float*)d_in[0];
    const float* W1  = (const float*)d_in[1];
    const float* b1  = (const float*)d_in[2];
    const float* W2  = (const float*)d_in[3];
    const float* b2  = (const float*)d_in[4];
    const int* esrc  = (const int*)d_in[5];
    const int* edst  = (const int*)d_in[6];
    const float* ew  = (const float*)d_in[7];

    const int E = in_sizes[5];
    const int n = out_size / NCLASS;  // 50000
    float* out = (float*)d_out;

    __half *sup1, *sup2, *w1t, *hacc;
    int *deg, *off, *cursor, *bsum;
    int2* csr;
    cudaGetSymbolAddress((void**)&sup1, g_sup1);
    cudaGetSymbolAddress((void**)&hacc, g_hacc);
    cudaGetSymbolAddress((void**)&sup2, g_sup2);
    cudaGetSymbolAddress((void**)&deg, g_deg);
    cudaGetSymbolAddress((void**)&off, g_off);
    cudaGetSymbolAddress((void**)&cursor, g_cursor);
    cudaGetSymbolAddress((void**)&bsum, g_bsum);
    cudaGetSymbolAddress((void**)&csr, g_csr);
    cudaGetSymbolAddress((void**)&w1t, g_w1t);

    // Dense layer-1 transform on tensor pipe (fp16 2-term split), fp16 out
    prep_w1_kernel<<<(NHID * NFEAT + 255) / 256, 256>>>(W1, w1t);
    gemm1_mma_kernel<<<(n + 127) / 128, 128>>>(x, w1t, sup1, n);

    // CSR build (by dst)
    cudaMemsetAsync(deg, 0, (size_t)n * sizeof(int));
    histogram_kernel<<<1184, 256>>>(edst, deg, E);
    scan_block_kernel<<<NBLK, SCAN_BLK>>>(deg, off, bsum, n);
    scan_bsum_kernel<<<1, 64>>>(bsum, NBLK);
    scan_fixup_kernel<<<(n + 255) / 256, 256>>>(off, cursor, bsum, n);
    scatter_kernel<<<1184, 256>>>(esrc, edst, ew, cursor, csr, E);

    // Layer 1 aggregate (fp16 gather, fp32 accumulate) + bias + ReLU, fp16 out
    spmm64_gather_kernel<<<(n * 32 + 255) / 256, 256>>>(csr, off, deg, sup1, b1, hacc, n);

    // Layer 2
    gemm2_kernel<<<n / 16, 256>>>(hacc, W2, sup2, n);
    spmm16_lsm_kernel<<<(n * 16 + 255) / 256, 256>>>(csr, off, deg, sup2, b2, out, n);
}